// round 1
// baseline (speedup 1.0000x reference)
#include <cuda_runtime.h>
#include <cstdint>

#define NWIN 64
#define HN 8
#define NQ 49
#define MT 50
#define HDIM 32
#define BWIN 4096
#define DIM 256
#define SCALE 0.17677669529663689f

// Precombined (mask + relative position bias) table: [w][h][qi][j], ~5 MB, L2-resident.
__device__ float g_bm[NWIN * HN * NQ * MT];

__global__ void precompute_bm_kernel(const float* __restrict__ mask,
                                     const float* __restrict__ bias_table,
                                     const int* __restrict__ rel_index) {
    int i = blockIdx.x * blockDim.x + threadIdx.x;
    if (i >= NWIN * HN * NQ * MT) return;
    int j  = i % MT;
    int r  = i / MT;
    int qi = r % NQ; r /= NQ;
    int h  = r % HN;
    int w  = r / HN;
    float v = mask[(w * NQ + qi) * MT + j];
    if (j > 0) {
        int idx = rel_index[qi * NQ + (j - 1)];
        v += bias_table[idx * HN + h];
    }
    g_bm[i] = v;
}

// ---- packed f32x2 helpers (sm_103a) ----
#define PACK2(d, lo, hi)  asm("mov.b64 %0, {%1, %2};" : "=l"(d) : "r"(lo), "r"(hi))
#define UNPACK2(lo, hi, s) asm("mov.b64 {%0, %1}, %2;" : "=r"(lo), "=r"(hi) : "l"(s))
#define FMA2(d, a, b, c)  asm("fma.rn.f32x2 %0, %1, %2, %3;" : "=l"(d) : "l"(a), "l"(b), "l"(c))
#define MUL2(d, a, b)     asm("mul.rn.f32x2 %0, %1, %2;" : "=l"(d) : "l"(a), "l"(b))
#define ADD2(d, a, b)     asm("add.rn.f32x2 %0, %1, %2;" : "=l"(d) : "l"(a), "l"(b))
#define LDSV2(a, b, addr) asm volatile("ld.shared.v2.b64 {%0, %1}, [%2];" : "=l"(a), "=l"(b) : "r"(addr))

__global__ void __launch_bounds__(64)
window_attn_kernel(const float* __restrict__ qkv, float* __restrict__ out) {
    const int bh = blockIdx.x;
    const int b  = bh >> 3;       // window index in [0, 4096)
    const int h  = bh & 7;        // head
    const int w  = b & (NWIN - 1);  // window-within-image (mask index)

    __shared__ float4 s_k[MT * 8];  // [token][8 x float4] = 50 x 32 fp32
    __shared__ float4 s_v[MT * 8];

    const float* base = qkv + (size_t)b * MT * (3 * DIM);
    const int t = threadIdx.x;

    // Stage K and V for this head into shared memory (coalesced float4 loads).
    for (int i = t; i < MT * 8; i += 64) {
        int m = i >> 3, c = i & 7;
        const float* row = base + m * (3 * DIM);
        s_k[i] = *(const float4*)(row + DIM     + h * HDIM + c * 4);
        s_v[i] = *(const float4*)(row + 2 * DIM + h * HDIM + c * 4);
    }
    __syncthreads();

    if (t >= NQ) return;
    const int qi = t;  // query row (token qi+1; cls token produces no query)

    const unsigned int skb = (unsigned int)__cvta_generic_to_shared(s_k);
    const unsigned int svb = (unsigned int)__cvta_generic_to_shared(s_v);

    // Load q row into 16 packed f32x2 registers and pre-scale.
    unsigned long long q[16];
    {
        const ulonglong2* qp =
            (const ulonglong2*)(base + (size_t)(qi + 1) * (3 * DIM) + h * HDIM);
        #pragma unroll
        for (int i2 = 0; i2 < 8; i2++) {
            ulonglong2 v2 = qp[i2];
            q[2 * i2] = v2.x; q[2 * i2 + 1] = v2.y;
        }
        unsigned int su = __float_as_uint(SCALE);
        unsigned long long s2; PACK2(s2, su, su);
        #pragma unroll
        for (int i2 = 0; i2 < 16; i2++) MUL2(q[i2], q[i2], s2);
    }

    float attn[MT];
    const float* bm = g_bm + (size_t)((w * HN + h) * NQ + qi) * MT;

    // QK^T: two key rows per iteration, packed f32x2 dot products from smem broadcast.
    #pragma unroll
    for (int jj = 0; jj < MT / 2; jj++) {
        const unsigned int a0 = skb + (2 * jj) * 128;
        const unsigned int a1 = a0 + 128;
        unsigned long long accA, accB, accC, accD;
        {
            unsigned long long k0, k1, k2, k3;
            LDSV2(k0, k1, a0);
            LDSV2(k2, k3, a1);
            MUL2(accA, q[0], k0);
            MUL2(accB, q[1], k1);
            MUL2(accC, q[0], k2);
            MUL2(accD, q[1], k3);
        }
        #pragma unroll
        for (int cc = 1; cc < 8; cc++) {
            unsigned long long k0, k1, k2, k3;
            LDSV2(k0, k1, a0 + cc * 16);
            LDSV2(k2, k3, a1 + cc * 16);
            FMA2(accA, q[2 * cc],     k0, accA);
            FMA2(accB, q[2 * cc + 1], k1, accB);
            FMA2(accC, q[2 * cc],     k2, accC);
            FMA2(accD, q[2 * cc + 1], k3, accD);
        }
        ADD2(accA, accA, accB);
        ADD2(accC, accC, accD);
        float2 bm2 = *(const float2*)(bm + 2 * jj);
        unsigned int lo, hi;
        UNPACK2(lo, hi, accA);
        attn[2 * jj]     = __uint_as_float(lo) + __uint_as_float(hi) + bm2.x;
        UNPACK2(lo, hi, accC);
        attn[2 * jj + 1] = __uint_as_float(lo) + __uint_as_float(hi) + bm2.y;
    }

    // Row-local softmax (attn row lives entirely in registers).
    float mx = attn[0];
    #pragma unroll
    for (int j = 1; j < MT; j++) mx = fmaxf(mx, attn[j]);
    float s0 = 0.f, s1 = 0.f;
    #pragma unroll
    for (int j = 0; j < MT; j += 2) {
        attn[j]     = __expf(attn[j]     - mx); s0 += attn[j];
        attn[j + 1] = __expf(attn[j + 1] - mx); s1 += attn[j + 1];
    }
    const float inv = 1.0f / (s0 + s1);

    // PV: accumulate output row (32 floats = 16 packed pairs).
    unsigned long long o[16];
    #pragma unroll
    for (int i2 = 0; i2 < 16; i2++) o[i2] = 0ULL;
    #pragma unroll
    for (int j = 0; j < MT; j++) {
        unsigned int au = __float_as_uint(attn[j]);
        unsigned long long a2; PACK2(a2, au, au);
        const unsigned int av = svb + j * 128;
        #pragma unroll
        for (int cc = 0; cc < 8; cc++) {
            unsigned long long v0, v1;
            LDSV2(v0, v1, av + cc * 16);
            FMA2(o[2 * cc],     a2, v0, o[2 * cc]);
            FMA2(o[2 * cc + 1], a2, v1, o[2 * cc + 1]);
        }
    }
    // Normalize once at the end (16 packed muls instead of 50 scalar muls).
    unsigned int iu = __float_as_uint(inv);
    unsigned long long inv2; PACK2(inv2, iu, iu);
    #pragma unroll
    for (int i2 = 0; i2 < 16; i2++) MUL2(o[i2], o[i2], inv2);

    ulonglong2* op = (ulonglong2*)(out + ((size_t)b * NQ + qi) * DIM + h * HDIM);
    #pragma unroll
    for (int i2 = 0; i2 < 8; i2++) {
        ulonglong2 v2; v2.x = o[2 * i2]; v2.y = o[2 * i2 + 1];
        op[i2] = v2;
    }
}

extern "C" void kernel_launch(void* const* d_in, const int* in_sizes, int n_in,
                              void* d_out, int out_size) {
    const float* qkv        = (const float*)d_in[0];
    const float* mask       = (const float*)d_in[1];
    const float* bias_table = (const float*)d_in[2];
    const int*   rel_index  = (const int*)d_in[3];
    float* out = (float*)d_out;

    const int total = NWIN * HN * NQ * MT;
    precompute_bm_kernel<<<(total + 255) / 256, 256>>>(mask, bias_table, rel_index);
    window_attn_kernel<<<BWIN * HN, 64>>>(qkv, out);
}